// round 1
// baseline (speedup 1.0000x reference)
#include <cuda_runtime.h>
#include <math.h>

// ---------------------------------------------------------------------------
// GPT-2 124M forward pass, FP32 baseline.
// B=4, T=1024, C=768, NH=12, HD=64, NL=12, V=50257
// ---------------------------------------------------------------------------

#define BB   4
#define TT   1024
#define BT   4096        // B*T
#define CC   768
#define C3   2304
#define C4   3072
#define NHH  12
#define HDD  64
#define NLYR 12
#define VV   50257
#define BHN  48          // B*NH

// Scratch (static device globals — no allocation allowed)
__device__ float g_x  [(size_t)BT * CC];
__device__ float g_h  [(size_t)BT * CC];
__device__ float g_qkv[(size_t)BT * C3];
__device__ float g_att[(size_t)BHN * TT * TT];   // 201 MB
__device__ float g_y  [(size_t)BT * CC];
__device__ float g_fc [(size_t)BT * C4];
__device__ float g_nll[BT];

// ---------------------------------------------------------------------------
// Generic tiled GEMM, C = A(MxK) @ B(KxN), row-major, fp32.
// EPI: 0 = bias (opt), 1 = bias+gelu, 2 = bias+residual-add (R)
// Batched via blockIdx.z with (outer,inner) offset decomposition:
//   off = (z/innerCnt)*Outer + (z%innerCnt)*Inner     (innerCnt==0 -> none)
// Assumes: M % BM == 0, K % BK == 0.  N is guarded.
// ---------------------------------------------------------------------------
template<int BM, int BN, int BK, int TM, int TN, int EPI>
__global__ void gemm_nn(const float* __restrict__ A, const float* __restrict__ Bm,
                        const float* __restrict__ bias, const float* __restrict__ R,
                        float* __restrict__ C,
                        int M, int N, int K, int lda, int ldb, int ldc,
                        long aO, long aI, long bO, long bI, long cO, long cI,
                        int innerCnt)
{
    constexpr int THREADS = (BM / TM) * (BN / TN);
    if (innerCnt > 0) {
        int z  = blockIdx.z;
        int zo = z / innerCnt, zi = z % innerCnt;
        A  += zo * aO + zi * aI;
        Bm += zo * bO + zi * bI;
        C  += zo * cO + zi * cI;
    }
    __shared__ float As[BK][BM + 4];
    __shared__ float Bs[BK][BN + 4];

    const int tid = threadIdx.x;
    const int tx  = tid % (BN / TN);
    const int ty  = tid / (BN / TN);
    const int m0  = blockIdx.y * BM;
    const int n0  = blockIdx.x * BN;

    float acc[TM][TN];
#pragma unroll
    for (int i = 0; i < TM; i++)
#pragma unroll
        for (int j = 0; j < TN; j++) acc[i][j] = 0.f;

    for (int k0 = 0; k0 < K; k0 += BK) {
        // load A tile (transposed into As), M assumed in-bounds
        for (int i = tid; i < BM * (BK / 4); i += THREADS) {
            int r  = i / (BK / 4);
            int kc = (i % (BK / 4)) * 4;
            float4 v = *(const float4*)(A + (size_t)(m0 + r) * lda + k0 + kc);
            As[kc + 0][r] = v.x; As[kc + 1][r] = v.y;
            As[kc + 2][r] = v.z; As[kc + 3][r] = v.w;
        }
        // load B tile
        for (int i = tid; i < BK * (BN / 4); i += THREADS) {
            int kk = i / (BN / 4);
            int nc = (i % (BN / 4)) * 4;
            int n  = n0 + nc;
            float4 v;
            const float* bp = Bm + (size_t)(k0 + kk) * ldb + n;
            if (n + 3 < N) v = *(const float4*)bp;
            else {
                v.x = (n + 0 < N) ? bp[0] : 0.f;
                v.y = (n + 1 < N) ? bp[1] : 0.f;
                v.z = (n + 2 < N) ? bp[2] : 0.f;
                v.w = (n + 3 < N) ? bp[3] : 0.f;
            }
            *(float4*)&Bs[kk][nc] = v;
        }
        __syncthreads();
#pragma unroll
        for (int kk = 0; kk < BK; kk++) {
            float a[TM], b[TN];
#pragma unroll
            for (int i = 0; i < TM; i++) a[i] = As[kk][ty * TM + i];
#pragma unroll
            for (int j = 0; j < TN; j++) b[j] = Bs[kk][tx * TN + j];
#pragma unroll
            for (int i = 0; i < TM; i++)
#pragma unroll
                for (int j = 0; j < TN; j++) acc[i][j] += a[i] * b[j];
        }
        __syncthreads();
    }

#pragma unroll
    for (int i = 0; i < TM; i++) {
        int m = m0 + ty * TM + i;
#pragma unroll
        for (int j = 0; j < TN; j++) {
            int n = n0 + tx * TN + j;
            if (n < N) {
                float v = acc[i][j];
                if (bias) v += bias[n];
                if (EPI == 1) {  // tanh gelu
                    float u = v;
                    float t = 0.7978845608028654f * (u + 0.044715f * u * u * u);
                    v = 0.5f * u * (1.f + tanhf(t));
                } else if (EPI == 2) {
                    v += R[(size_t)m * ldc + n];
                }
                C[(size_t)m * ldc + n] = v;
            }
        }
    }
}

// ---------------------------------------------------------------------------
// GEMM NT: C = alpha * A(MxK) @ B(NxK)^T   (row-major A, row-major B)
// SKIP_UPPER: skip blocks fully above causal diagonal (scores only)
// ---------------------------------------------------------------------------
template<int BM, int BN, int BK, int TM, int TN, bool SKIP_UPPER>
__global__ void gemm_nt(const float* __restrict__ A, const float* __restrict__ Bm,
                        float* __restrict__ C,
                        int M, int N, int K, int lda, int ldb, int ldc, float alpha,
                        long aO, long aI, long bO, long bI, long cO, long cI,
                        int innerCnt)
{
    constexpr int THREADS = (BM / TM) * (BN / TN);
    const int m0 = blockIdx.y * BM;
    const int n0 = blockIdx.x * BN;
    if (SKIP_UPPER && n0 > m0 + BM - 1) return;  // fully masked block

    if (innerCnt > 0) {
        int z  = blockIdx.z;
        int zo = z / innerCnt, zi = z % innerCnt;
        A  += zo * aO + zi * aI;
        Bm += zo * bO + zi * bI;
        C  += zo * cO + zi * cI;
    }
    __shared__ float As[BK][BM + 4];
    __shared__ float Bs[BK][BN + 4];

    const int tid = threadIdx.x;
    const int tx  = tid % (BN / TN);
    const int ty  = tid / (BN / TN);

    float acc[TM][TN];
#pragma unroll
    for (int i = 0; i < TM; i++)
#pragma unroll
        for (int j = 0; j < TN; j++) acc[i][j] = 0.f;

    for (int k0 = 0; k0 < K; k0 += BK) {
        for (int i = tid; i < BM * (BK / 4); i += THREADS) {
            int r  = i / (BK / 4);
            int kc = (i % (BK / 4)) * 4;
            float4 v = *(const float4*)(A + (size_t)(m0 + r) * lda + k0 + kc);
            As[kc + 0][r] = v.x; As[kc + 1][r] = v.y;
            As[kc + 2][r] = v.z; As[kc + 3][r] = v.w;
        }
        for (int i = tid; i < BN * (BK / 4); i += THREADS) {
            int nrow = i / (BK / 4);
            int kc   = (i % (BK / 4)) * 4;
            float4 v = make_float4(0.f, 0.f, 0.f, 0.f);
            if (n0 + nrow < N)
                v = *(const float4*)(Bm + (size_t)(n0 + nrow) * ldb + k0 + kc);
            Bs[kc + 0][nrow] = v.x; Bs[kc + 1][nrow] = v.y;
            Bs[kc + 2][nrow] = v.z; Bs[kc + 3][nrow] = v.w;
        }
        __syncthreads();
#pragma unroll
        for (int kk = 0; kk < BK; kk++) {
            float a[TM], b[TN];
#pragma unroll
            for (int i = 0; i < TM; i++) a[i] = As[kk][ty * TM + i];
#pragma unroll
            for (int j = 0; j < TN; j++) b[j] = Bs[kk][tx * TN + j];
#pragma unroll
            for (int i = 0; i < TM; i++)
#pragma unroll
                for (int j = 0; j < TN; j++) acc[i][j] += a[i] * b[j];
        }
        __syncthreads();
    }

#pragma unroll
    for (int i = 0; i < TM; i++) {
        int m = m0 + ty * TM + i;
#pragma unroll
        for (int j = 0; j < TN; j++) {
            int n = n0 + tx * TN + j;
            if (n < N) C[(size_t)m * ldc + n] = acc[i][j] * alpha;
        }
    }
}

// ---------------------------------------------------------------------------
// Causal softmax on g_att rows. grid = (T, B*NH), 256 threads.
// Writes probs for j <= t, zeros for j > t (so PV GEMM can run dense).
// ---------------------------------------------------------------------------
__global__ void softmax_causal(float* __restrict__ att)
{
    const int t = blockIdx.x;
    float* row = att + ((size_t)blockIdx.y * TT + t) * TT;
    const int n = t + 1;
    __shared__ float red[256];
    const int tid = threadIdx.x;

    float mx = -1e30f;
    for (int j = tid; j < n; j += 256) mx = fmaxf(mx, row[j]);
    red[tid] = mx; __syncthreads();
    for (int s = 128; s > 0; s >>= 1) {
        if (tid < s) red[tid] = fmaxf(red[tid], red[tid + s]);
        __syncthreads();
    }
    mx = red[0]; __syncthreads();

    float sum = 0.f;
    for (int j = tid; j < n; j += 256) sum += expf(row[j] - mx);
    red[tid] = sum; __syncthreads();
    for (int s = 128; s > 0; s >>= 1) {
        if (tid < s) red[tid] += red[tid + s];
        __syncthreads();
    }
    const float inv = 1.f / red[0];

    for (int j = tid; j < n; j += 256) row[j] = expf(row[j] - mx) * inv;
    for (int j = n + tid; j < TT; j += 256) row[j] = 0.f;
}

// ---------------------------------------------------------------------------
// LayerNorm: one block per row (C=768), 256 threads.
// ---------------------------------------------------------------------------
__global__ void layernorm_k(const float* __restrict__ x, const float* __restrict__ g,
                            const float* __restrict__ b, float* __restrict__ y)
{
    const int row = blockIdx.x;
    const float* xr = x + (size_t)row * CC;
    __shared__ float s1[256], s2[256];
    const int tid = threadIdx.x;
    float a = 0.f, sq = 0.f;
    for (int c = tid; c < CC; c += 256) { float v = xr[c]; a += v; sq += v * v; }
    s1[tid] = a; s2[tid] = sq; __syncthreads();
    for (int s = 128; s > 0; s >>= 1) {
        if (tid < s) { s1[tid] += s1[tid + s]; s2[tid] += s2[tid + s]; }
        __syncthreads();
    }
    const float mean = s1[0] / CC;
    const float var  = s2[0] / CC - mean * mean;
    const float rstd = rsqrtf(var + 1e-5f);
    float* yr = y + (size_t)row * CC;
    for (int c = tid; c < CC; c += 256)
        yr[c] = (xr[c] - mean) * rstd * g[c] + b[c];
}

// ---------------------------------------------------------------------------
// Token + position embedding
// ---------------------------------------------------------------------------
__global__ void embed_k(const int* __restrict__ tok, const float* __restrict__ wte,
                        const float* __restrict__ wpe, float* __restrict__ x)
{
    const int idx = blockIdx.x * blockDim.x + threadIdx.x;
    if (idx >= BT * CC) return;
    const int bt = idx / CC, c = idx % CC;
    const int t  = bt % TT;
    x[idx] = wte[(size_t)tok[bt] * CC + c] + wpe[(size_t)t * CC + c];
}

// ---------------------------------------------------------------------------
// Per-row NLL from logits (2 passes over V=50257)
// ---------------------------------------------------------------------------
__global__ void nll_k(const float* __restrict__ logits, const int* __restrict__ target,
                      float* __restrict__ nll)
{
    const int bt = blockIdx.x;
    const float* row = logits + (size_t)bt * VV;
    __shared__ float red[256];
    const int tid = threadIdx.x;

    float mx = -1e30f;
    for (int j = tid; j < VV; j += 256) mx = fmaxf(mx, row[j]);
    red[tid] = mx; __syncthreads();
    for (int s = 128; s > 0; s >>= 1) {
        if (tid < s) red[tid] = fmaxf(red[tid], red[tid + s]);
        __syncthreads();
    }
    mx = red[0]; __syncthreads();

    float sum = 0.f;
    for (int j = tid; j < VV; j += 256) sum += expf(row[j] - mx);
    red[tid] = sum; __syncthreads();
    for (int s = 128; s > 0; s >>= 1) {
        if (tid < s) red[tid] += red[tid + s];
        __syncthreads();
    }
    if (tid == 0)
        nll[bt] = logf(red[0]) + mx - row[target[bt]];
}

__global__ void mean_k(const float* __restrict__ nll, float* __restrict__ out)
{
    __shared__ float red[256];
    const int tid = threadIdx.x;
    float s = 0.f;
    for (int i = tid; i < BT; i += 256) s += nll[i];
    red[tid] = s; __syncthreads();
    for (int st = 128; st > 0; st >>= 1) {
        if (tid < st) red[tid] += red[tid + st];
        __syncthreads();
    }
    if (tid == 0) out[0] = red[0] / (float)BT;
}

// ---------------------------------------------------------------------------
// Launch
// ---------------------------------------------------------------------------
extern "C" void kernel_launch(void* const* d_in, const int* in_sizes, int n_in,
                              void* d_out, int out_size)
{
    const int*   tokens = (const int*)  d_in[0];
    const int*   target = (const int*)  d_in[1];
    const float* wte    = (const float*)d_in[2];
    const float* wpe    = (const float*)d_in[3];
    const float* ln1_g  = (const float*)d_in[4];
    const float* ln1_b  = (const float*)d_in[5];
    const float* attn_w = (const float*)d_in[6];
    const float* attn_b = (const float*)d_in[7];
    const float* proj_w = (const float*)d_in[8];
    const float* proj_b = (const float*)d_in[9];
    const float* ln2_g  = (const float*)d_in[10];
    const float* ln2_b  = (const float*)d_in[11];
    const float* fc_w   = (const float*)d_in[12];
    const float* fc_b   = (const float*)d_in[13];
    const float* fc2_w  = (const float*)d_in[14];
    const float* fc2_b  = (const float*)d_in[15];
    const float* lnf_g  = (const float*)d_in[16];
    const float* lnf_b  = (const float*)d_in[17];
    float* out = (float*)d_out;

    float *x, *h, *qkv, *att, *y, *fc, *nll;
    cudaGetSymbolAddress((void**)&x,   g_x);
    cudaGetSymbolAddress((void**)&h,   g_h);
    cudaGetSymbolAddress((void**)&qkv, g_qkv);
    cudaGetSymbolAddress((void**)&att, g_att);
    cudaGetSymbolAddress((void**)&y,   g_y);
    cudaGetSymbolAddress((void**)&fc,  g_fc);
    cudaGetSymbolAddress((void**)&nll, g_nll);

    // embed
    embed_k<<<(BT * CC + 255) / 256, 256>>>(tokens, wte, wpe, x);

    const long L1M = (long)TT * TT;          // per-head att stride
    const long QB  = (long)TT * C3;          // per-batch qkv stride

    for (int l = 0; l < NLYR; l++) {
        const float* aw  = attn_w + (size_t)l * CC * C3;
        const float* ab  = attn_b + (size_t)l * C3;
        const float* pw  = proj_w + (size_t)l * CC * CC;
        const float* pb  = proj_b + (size_t)l * CC;
        const float* fw  = fc_w   + (size_t)l * CC * C4;
        const float* fb  = fc_b   + (size_t)l * C4;
        const float* f2w = fc2_w  + (size_t)l * C4 * CC;
        const float* f2b = fc2_b  + (size_t)l * CC;

        // LN1
        layernorm_k<<<BT, 256>>>(x, ln1_g + l * CC, ln1_b + l * CC, h);

        // QKV: [4096,768] @ [768,2304] + bias
        gemm_nn<128,128,16,8,8,0><<<dim3(C3/128, BT/128), 256>>>(
            h, aw, ab, nullptr, qkv, BT, C3, CC, CC, C3, C3,
            0,0,0,0,0,0, 0);

        // scores: S[b,h] = Q @ K^T * 1/8   (batched over 48 heads)
        gemm_nt<128,128,16,8,8,true><<<dim3(TT/128, TT/128, BHN), 256>>>(
            qkv, qkv + CC, att, TT, TT, HDD, C3, C3, TT, 0.125f,
            QB, HDD,          // A (Q):  b -> +T*3C, h -> +64
            QB, HDD,          // B (K):  same (base already +768)
            (long)NHH * L1M, L1M,   // C: z*1M
            NHH);

        // causal softmax
        softmax_causal<<<dim3(TT, BHN), 256>>>(att);

        // Y[b,h] = S @ V   -> g_y [4096, 768]
        gemm_nn<128,64,16,8,4,0><<<dim3(1, TT/128, BHN), 256>>>(
            att, qkv + 2 * CC, nullptr, nullptr, y, TT, HDD, TT, TT, C3, CC,
            (long)NHH * L1M, L1M,   // A (S)
            QB, HDD,                // B (V)
            (long)TT * CC, HDD,     // C (y): b -> +T*C, h -> +64
            NHH);

        // x = x + Y @ proj_w + proj_b
        gemm_nn<128,128,16,8,8,2><<<dim3(CC/128, BT/128), 256>>>(
            y, pw, pb, x, x, BT, CC, CC, CC, CC, CC,
            0,0,0,0,0,0, 0);

        // LN2
        layernorm_k<<<BT, 256>>>(x, ln2_g + l * CC, ln2_b + l * CC, h);

        // FC + gelu: [4096,768] @ [768,3072]
        gemm_nn<128,128,16,8,8,1><<<dim3(C4/128, BT/128), 256>>>(
            h, fw, fb, nullptr, fc, BT, C4, CC, CC, C4, C4,
            0,0,0,0,0,0, 0);

        // x = x + FCout @ fc2_w + fc2_b
        gemm_nn<128,128,16,8,8,2><<<dim3(CC/128, BT/128), 256>>>(
            fc, f2w, f2b, x, x, BT, CC, C4, C4, CC, CC,
            0,0,0,0,0,0, 0);
    }

    // final LN
    layernorm_k<<<BT, 256>>>(x, lnf_g, lnf_b, h);

    // logits = h @ wte^T : [4096,768] @ [50257,768]^T -> d_out
    gemm_nt<128,128,16,8,8,false><<<dim3((VV + 127) / 128, BT / 128), 256>>>(
        h, wte, out, BT, VV, CC, CC, CC, VV, 1.0f,
        0,0,0,0,0,0, 0);

    // loss
    nll_k<<<BT, 256>>>(out, target, nll);
    mean_k<<<1, 256>>>(nll, out + (out_size - 1));
}

// round 2
// speedup vs baseline: 2.4156x; 2.4156x over previous
#include <cuda_runtime.h>
#include <cuda_bf16.h>
#include <math.h>

// ---------------------------------------------------------------------------
// GPT-2 124M forward, bf16x2 (hi/lo split) tensor-core GEMMs, fp32 elsewhere.
// B=4, T=1024, C=768, NH=12, HD=64, NL=12, V=50257
// ---------------------------------------------------------------------------

#define BB   4
#define TT   1024
#define BT   4096
#define CC   768
#define C3   2304
#define C4   3072
#define NHH  12
#define HDD  64
#define NLYR 12
#define VV   50257
#define BHN  48

// Scratch (static device globals — no allocation allowed)
__device__ float g_x  [(size_t)BT * CC];
__device__ float g_h  [(size_t)BT * CC];
__device__ float g_qkv[(size_t)BT * C3];
__device__ float g_att[(size_t)BHN * TT * TT];
__device__ float g_y  [(size_t)BT * CC];
__device__ float g_fc [(size_t)BT * C4];
__device__ float g_nll[BT];

// ---------------------------------------------------------------------------
// mma / ldmatrix helpers
// ---------------------------------------------------------------------------
__device__ __forceinline__ void ldsm_x4(unsigned a, unsigned* r) {
    asm volatile("ldmatrix.sync.aligned.m8n8.x4.shared.b16 {%0,%1,%2,%3},[%4];"
                 : "=r"(r[0]), "=r"(r[1]), "=r"(r[2]), "=r"(r[3]) : "r"(a));
}
__device__ __forceinline__ void ldsm_x4_t(unsigned a, unsigned* r) {
    asm volatile("ldmatrix.sync.aligned.m8n8.x4.trans.shared.b16 {%0,%1,%2,%3},[%4];"
                 : "=r"(r[0]), "=r"(r[1]), "=r"(r[2]), "=r"(r[3]) : "r"(a));
}
__device__ __forceinline__ void mma16816(float* c, const unsigned* a, const unsigned* b) {
    asm volatile("mma.sync.aligned.m16n8k16.row.col.f32.bf16.bf16.f32 "
                 "{%0,%1,%2,%3},{%4,%5,%6,%7},{%8,%9},{%0,%1,%2,%3};"
                 : "+f"(c[0]), "+f"(c[1]), "+f"(c[2]), "+f"(c[3])
                 : "r"(a[0]), "r"(a[1]), "r"(a[2]), "r"(a[3]), "r"(b[0]), "r"(b[1]));
}

// split 4 floats into packed bf16 hi / lo pairs
__device__ __forceinline__ void split_pack(float4 v, unsigned* hi, unsigned* lo) {
    __nv_bfloat162 h01 = __floats2bfloat162_rn(v.x, v.y);
    __nv_bfloat162 h23 = __floats2bfloat162_rn(v.z, v.w);
    float2 f01 = __bfloat1622float2(h01);
    float2 f23 = __bfloat1622float2(h23);
    __nv_bfloat162 l01 = __floats2bfloat162_rn(v.x - f01.x, v.y - f01.y);
    __nv_bfloat162 l23 = __floats2bfloat162_rn(v.z - f23.x, v.w - f23.y);
    hi[0] = *(unsigned*)&h01; hi[1] = *(unsigned*)&h23;
    lo[0] = *(unsigned*)&l01; lo[1] = *(unsigned*)&l23;
}

__device__ __forceinline__ float gelu_f(float u) {
    float t = 0.7978845608028654f * (u + 0.044715f * u * u * u);
    return 0.5f * u * (1.f + tanhf(t));
}

// ---------------------------------------------------------------------------
// Tensor-core GEMM.
//   NT=false: C = A[M,K] @ B[K,N]         (B row-major [K][N])
//   NT=true : C = alpha * A[M,K] @ B[N,K]^T
// EPI: 0 alpha only, 1 +bias, 2 +bias+gelu, 3 +bias+residual
// 256 threads, 8 warps in (BM/WM) x (BN/WN) arrangement, BK=16, double buffer.
// Requires M % BM == 0, K % 16 == 0. N guarded (NT fill + all stores).
// ---------------------------------------------------------------------------
template<int BM, int BN, int WM, int WN, int EPI, bool NT, bool SKIP>
__global__ __launch_bounds__(256)
void gemm_tc(const float* __restrict__ A, const float* __restrict__ B,
             const float* __restrict__ bias, const float* __restrict__ R,
             float* __restrict__ C, int M, int N, int K,
             int lda, int ldb, int ldc, float alpha,
             long aO, long aI, long bO, long bI, long cO, long cI, int innerCnt)
{
    constexpr int BK  = 16;
    constexpr int BKP = 24;        // padded k-stride (48B, 16B-aligned rows)
    constexpr int BNP = BN + 8;    // padded n-stride for NN B tile
    constexpr int WARPS_N = BN / WN;
    constexpr int MI = WM / 16;    // m-frags per warp
    constexpr int NF = WN / 8;     // n-frags per warp
    constexpr int NP = NF / 2;     // ldmatrix x4 pairs
    constexpr int ALD = (BM * BK / 4) / 256;
    constexpr int BLD = (BN * BK / 4) / 256;
    static_assert((BM / WM) * (BN / WN) == 8, "8 warps");

    const int m0 = blockIdx.y * BM;
    const int n0 = blockIdx.x * BN;
    if (SKIP && n0 > m0 + BM - 1) return;

    if (innerCnt > 0) {
        int z = blockIdx.z, zo = z / innerCnt, zi = z % innerCnt;
        A += zo * aO + zi * aI;
        B += zo * bO + zi * bI;
        C += zo * cO + zi * cI;
    }

    constexpr int ABYTES = 2 * BM * BKP * 2;                       // hi+lo
    constexpr int BBYTES = NT ? 2 * BN * BKP * 2 : 2 * BK * BNP * 2;
    __shared__ __align__(16) char smem[2 * (ABYTES + BBYTES)];

    const int tid = threadIdx.x, lane = tid & 31, w = tid >> 5;
    const int wm = w / WARPS_N, wn = w % WARPS_N;

    float acc[MI][NF][4];
#pragma unroll
    for (int i = 0; i < MI; i++)
#pragma unroll
        for (int j = 0; j < NF; j++)
#pragma unroll
            for (int q = 0; q < 4; q++) acc[i][j][q] = 0.f;

    float4 pa[ALD], pb[BLD];

    auto loadG = [&](int t) {
#pragma unroll
        for (int j = 0; j < ALD; j++) {
            int i = tid + 256 * j;
            int r = i >> 2, kc = (i & 3) * 4;
            pa[j] = *(const float4*)(A + (size_t)(m0 + r) * lda + t * BK + kc);
        }
#pragma unroll
        for (int j = 0; j < BLD; j++) {
            int i = tid + 256 * j;
            if (NT) {
                int nr = i >> 2, kc = (i & 3) * 4;
                if (n0 + nr < N)
                    pb[j] = *(const float4*)(B + (size_t)(n0 + nr) * ldb + t * BK + kc);
                else
                    pb[j] = make_float4(0.f, 0.f, 0.f, 0.f);
            } else {
                int kk = i / (BN / 4), nc = (i % (BN / 4)) * 4;
                pb[j] = *(const float4*)(B + (size_t)(t * BK + kk) * ldb + n0 + nc);
            }
        }
    };

    auto storeS = [&](int buf) {
        char* base = smem + buf * (ABYTES + BBYTES);
        __nv_bfloat16* Ah = (__nv_bfloat16*)base;
        __nv_bfloat16* Al = Ah + BM * BKP;
        __nv_bfloat16* Bh = (__nv_bfloat16*)(base + ABYTES);
        __nv_bfloat16* Bl = Bh + (NT ? BN * BKP : BK * BNP);
#pragma unroll
        for (int j = 0; j < ALD; j++) {
            int i = tid + 256 * j;
            int r = i >> 2, kc = (i & 3) * 4;
            unsigned hi[2], lo[2];
            split_pack(pa[j], hi, lo);
            *(uint2*)&Ah[r * BKP + kc] = make_uint2(hi[0], hi[1]);
            *(uint2*)&Al[r * BKP + kc] = make_uint2(lo[0], lo[1]);
        }
#pragma unroll
        for (int j = 0; j < BLD; j++) {
            int i = tid + 256 * j;
            unsigned hi[2], lo[2];
            split_pack(pb[j], hi, lo);
            if (NT) {
                int nr = i >> 2, kc = (i & 3) * 4;
                *(uint2*)&Bh[nr * BKP + kc] = make_uint2(hi[0], hi[1]);
                *(uint2*)&Bl[nr * BKP + kc] = make_uint2(lo[0], lo[1]);
            } else {
                int kk = i / (BN / 4), nc = (i % (BN / 4)) * 4;
                *(uint2*)&Bh[kk * BNP + nc] = make_uint2(hi[0], hi[1]);
                *(uint2*)&Bl[kk * BNP + nc] = make_uint2(lo[0], lo[1]);
            }
        }
    };

    const int nt = K / BK;
    loadG(0);
    storeS(0);
    __syncthreads();

    for (int t = 0; t < nt; t++) {
        const int buf = t & 1;
        if (t + 1 < nt) loadG(t + 1);

        char* base = smem + buf * (ABYTES + BBYTES);
        unsigned sAh = (unsigned)__cvta_generic_to_shared(base);
        unsigned sAl = sAh + BM * BKP * 2;
        unsigned sBh = (unsigned)__cvta_generic_to_shared(base + ABYTES);
        unsigned sBl = sBh + (NT ? BN * BKP : BK * BNP) * 2;

        // A fragments (hi & lo) for this k16 step
        unsigned a_h[MI][4], a_l[MI][4];
        {
            const int arow = (lane & 15);
            const int acol = (lane >> 4) * 8;
#pragma unroll
            for (int mi = 0; mi < MI; mi++) {
                unsigned off = ((wm * WM + mi * 16 + arow) * BKP + acol) * 2;
                ldsm_x4(sAh + off, a_h[mi]);
                ldsm_x4(sAl + off, a_l[mi]);
            }
        }

#pragma unroll
        for (int p = 0; p < NP; p++) {
            unsigned b_h[4], b_l[4];
            if (NT) {
                const int nrow = (lane & 7) | ((lane >> 4) << 3);
                const int kcol = ((lane >> 3) & 1) * 8;
                unsigned off = ((wn * WN + p * 16 + nrow) * BKP + kcol) * 2;
                ldsm_x4(sBh + off, b_h);
                ldsm_x4(sBl + off, b_l);
            } else {
                const int krow = lane & 15;
                const int ncol = wn * WN + p * 16 + (lane >> 4) * 8;
                unsigned off = (krow * BNP + ncol) * 2;
                ldsm_x4_t(sBh + off, b_h);
                ldsm_x4_t(sBl + off, b_l);
            }
#pragma unroll
            for (int mi = 0; mi < MI; mi++) {
                mma16816(acc[mi][2 * p],     a_h[mi], b_h);
                mma16816(acc[mi][2 * p],     a_h[mi], b_l);
                mma16816(acc[mi][2 * p],     a_l[mi], b_h);
                mma16816(acc[mi][2 * p + 1], a_h[mi], b_h + 2);
                mma16816(acc[mi][2 * p + 1], a_h[mi], b_l + 2);
                mma16816(acc[mi][2 * p + 1], a_l[mi], b_h + 2);
            }
        }

        if (t + 1 < nt) {
            storeS(buf ^ 1);
            __syncthreads();
        }
    }

    // epilogue
    const int g = lane >> 2, tg = lane & 3;
#pragma unroll
    for (int mi = 0; mi < MI; mi++) {
#pragma unroll
        for (int nf = 0; nf < NF; nf++) {
            int col = n0 + wn * WN + nf * 8 + tg * 2;
#pragma unroll
            for (int h = 0; h < 2; h++) {
                int row = m0 + wm * WM + mi * 16 + g + h * 8;
                float v0 = acc[mi][nf][2 * h]     * alpha;
                float v1 = acc[mi][nf][2 * h + 1] * alpha;
                if (EPI >= 1) {
                    if (col     < N) v0 += bias[col];
                    if (col + 1 < N) v1 += bias[col + 1];
                }
                if (EPI == 2) { v0 = gelu_f(v0); v1 = gelu_f(v1); }
                if (EPI == 3) {
                    if (col     < N) v0 += R[(size_t)row * ldc + col];
                    if (col + 1 < N) v1 += R[(size_t)row * ldc + col + 1];
                }
                if (col     < N) C[(size_t)row * ldc + col]     = v0;
                if (col + 1 < N) C[(size_t)row * ldc + col + 1] = v1;
            }
        }
    }
}

// ---------------------------------------------------------------------------
// Causal softmax on att rows. grid = (T, B*NH), 256 threads.
// ---------------------------------------------------------------------------
__global__ void softmax_causal(float* __restrict__ att)
{
    const int t = blockIdx.x;
    float* row = att + ((size_t)blockIdx.y * TT + t) * TT;
    const int n = t + 1;
    __shared__ float red[256];
    const int tid = threadIdx.x;

    float mx = -1e30f;
    for (int j = tid; j < n; j += 256) mx = fmaxf(mx, row[j]);
    red[tid] = mx; __syncthreads();
    for (int s = 128; s > 0; s >>= 1) {
        if (tid < s) red[tid] = fmaxf(red[tid], red[tid + s]);
        __syncthreads();
    }
    mx = red[0]; __syncthreads();

    float sum = 0.f;
    for (int j = tid; j < n; j += 256) sum += expf(row[j] - mx);
    red[tid] = sum; __syncthreads();
    for (int s = 128; s > 0; s >>= 1) {
        if (tid < s) red[tid] += red[tid + s];
        __syncthreads();
    }
    const float inv = 1.f / red[0];

    for (int j = tid; j < n; j += 256) row[j] = expf(row[j] - mx) * inv;
    for (int j = n + tid; j < TT; j += 256) row[j] = 0.f;
}

// ---------------------------------------------------------------------------
// LayerNorm: one block per row (C=768), 256 threads.
// ---------------------------------------------------------------------------
__global__ void layernorm_k(const float* __restrict__ x, const float* __restrict__ g,
                            const float* __restrict__ b, float* __restrict__ y)
{
    const int row = blockIdx.x;
    const float* xr = x + (size_t)row * CC;
    __shared__ float s1[256], s2[256];
    const int tid = threadIdx.x;
    float a = 0.f, sq = 0.f;
    for (int c = tid; c < CC; c += 256) { float v = xr[c]; a += v; sq += v * v; }
    s1[tid] = a; s2[tid] = sq; __syncthreads();
    for (int s = 128; s > 0; s >>= 1) {
        if (tid < s) { s1[tid] += s1[tid + s]; s2[tid] += s2[tid + s]; }
        __syncthreads();
    }
    const float mean = s1[0] / CC;
    const float var  = s2[0] / CC - mean * mean;
    const float rstd = rsqrtf(var + 1e-5f);
    float* yr = y + (size_t)row * CC;
    for (int c = tid; c < CC; c += 256)
        yr[c] = (xr[c] - mean) * rstd * g[c] + b[c];
}

__global__ void embed_k(const int* __restrict__ tok, const float* __restrict__ wte,
                        const float* __restrict__ wpe, float* __restrict__ x)
{
    const int idx = blockIdx.x * blockDim.x + threadIdx.x;
    if (idx >= BT * CC) return;
    const int bt = idx / CC, c = idx % CC;
    const int t  = bt % TT;
    x[idx] = wte[(size_t)tok[bt] * CC + c] + wpe[(size_t)t * CC + c];
}

__global__ void nll_k(const float* __restrict__ logits, const int* __restrict__ target,
                      float* __restrict__ nll)
{
    const int bt = blockIdx.x;
    const float* row = logits + (size_t)bt * VV;
    __shared__ float red[256];
    const int tid = threadIdx.x;

    float mx = -1e30f;
    for (int j = tid; j < VV; j += 256) mx = fmaxf(mx, row[j]);
    red[tid] = mx; __syncthreads();
    for (int s = 128; s > 0; s >>= 1) {
        if (tid < s) red[tid] = fmaxf(red[tid], red[tid + s]);
        __syncthreads();
    }
    mx = red[0]; __syncthreads();

    float sum = 0.f;
    for (int j = tid; j < VV; j += 256) sum += expf(row[j] - mx);
    red[tid] = sum; __syncthreads();
    for (int s = 128; s > 0; s >>= 1) {
        if (tid < s) red[tid] += red[tid + s];
        __syncthreads();
    }
    if (tid == 0)
        nll[bt] = logf(red[0]) + mx - row[target[bt]];
}

__global__ void mean_k(const float* __restrict__ nll, float* __restrict__ out)
{
    __shared__ float red[256];
    const int tid = threadIdx.x;
    float s = 0.f;
    for (int i = tid; i < BT; i += 256) s += nll[i];
    red[tid] = s; __syncthreads();
    for (int st = 128; st > 0; st >>= 1) {
        if (tid < st) red[tid] += red[tid + st];
        __syncthreads();
    }
    if (tid == 0) out[0] = red[0] / (float)BT;
}

// ---------------------------------------------------------------------------
// Launch
// ---------------------------------------------------------------------------
extern "C" void kernel_launch(void* const* d_in, const int* in_sizes, int n_in,
                              void* d_out, int out_size)
{
    const int*   tokens = (const int*)  d_in[0];
    const int*   target = (const int*)  d_in[1];
    const float* wte    = (const float*)d_in[2];
    const float* wpe    = (const float*)d_in[3];
    const float* ln1_g  = (const float*)d_in[4];
    const float* ln1_b  = (const float*)d_in[5];
    const float* attn_w = (const float*)d_in[6];
    const float* attn_b = (const float*)d_in[7];
    const float* proj_w = (const float*)d_in[8];
    const float* proj_b = (const float*)d_in[9];
    const float* ln2_g  = (const float*)d_in[10];
    const float* ln2_b  = (const float*)d_in[11];
    const float* fc_w   = (const float*)d_in[12];
    const float* fc_b   = (const float*)d_in[13];
    const float* fc2_w  = (const float*)d_in[14];
    const float* fc2_b  = (const float*)d_in[15];
    const float* lnf_g  = (const float*)d_in[16];
    const float* lnf_b  = (const float*)d_in[17];
    float* out = (float*)d_out;

    float *x, *h, *qkv, *att, *y, *fc, *nll;
    cudaGetSymbolAddress((void**)&x,   g_x);
    cudaGetSymbolAddress((void**)&h,   g_h);
    cudaGetSymbolAddress((void**)&qkv, g_qkv);
    cudaGetSymbolAddress((void**)&att, g_att);
    cudaGetSymbolAddress((void**)&y,   g_y);
    cudaGetSymbolAddress((void**)&fc,  g_fc);
    cudaGetSymbolAddress((void**)&nll, g_nll);

    embed_k<<<(BT * CC + 255) / 256, 256>>>(tokens, wte, wpe, x);

    const long L1M = (long)TT * TT;
    const long QB  = (long)TT * C3;

    for (int l = 0; l < NLYR; l++) {
        const float* aw  = attn_w + (size_t)l * CC * C3;
        const float* ab  = attn_b + (size_t)l * C3;
        const float* pw  = proj_w + (size_t)l * CC * CC;
        const float* pb  = proj_b + (size_t)l * CC;
        const float* fw  = fc_w   + (size_t)l * CC * C4;
        const float* fb  = fc_b   + (size_t)l * C4;
        const float* f2w = fc2_w  + (size_t)l * C4 * CC;
        const float* f2b = fc2_b  + (size_t)l * CC;

        layernorm_k<<<BT, 256>>>(x, ln1_g + l * CC, ln1_b + l * CC, h);

        // QKV: [4096,768] @ [768,2304] + bias
        gemm_tc<128,128,32,64,1,false,false><<<dim3(C3/128, BT/128), 256>>>(
            h, aw, ab, nullptr, qkv, BT, C3, CC, CC, C3, C3, 1.f,
            0,0,0,0,0,0, 0);

        // scores: S[b,h] = Q @ K^T * 1/8  (batched over 48 heads, causal skip)
        gemm_tc<128,128,32,64,0,true,true><<<dim3(TT/128, TT/128, BHN), 256>>>(
            qkv, qkv + CC, nullptr, nullptr, att, TT, TT, HDD, C3, C3, TT, 0.125f,
            QB, HDD, QB, HDD, (long)NHH * L1M, L1M, NHH);

        softmax_causal<<<dim3(TT, BHN), 256>>>(att);

        // Y[b,h] = S @ V
        gemm_tc<128,64,32,32,0,false,false><<<dim3(1, TT/128, BHN), 256>>>(
            att, qkv + 2 * CC, nullptr, nullptr, y, TT, HDD, TT, TT, C3, CC, 1.f,
            (long)NHH * L1M, L1M, QB, HDD, (long)TT * CC, HDD, NHH);

        // x = x + Y @ proj_w + proj_b
        gemm_tc<128,128,32,64,3,false,false><<<dim3(CC/128, BT/128), 256>>>(
            y, pw, pb, x, x, BT, CC, CC, CC, CC, CC, 1.f,
            0,0,0,0,0,0, 0);

        layernorm_k<<<BT, 256>>>(x, ln2_g + l * CC, ln2_b + l * CC, h);

        // FC + gelu
        gemm_tc<128,128,32,64,2,false,false><<<dim3(C4/128, BT/128), 256>>>(
            h, fw, fb, nullptr, fc, BT, C4, CC, CC, C4, C4, 1.f,
            0,0,0,0,0,0, 0);

        // x = x + FCout @ fc2_w + fc2_b
        gemm_tc<128,128,32,64,3,false,false><<<dim3(CC/128, BT/128), 256>>>(
            fc, f2w, f2b, x, x, BT, CC, C4, C4, CC, CC, 1.f,
            0,0,0,0,0,0, 0);
    }

    layernorm_k<<<BT, 256>>>(x, lnf_g, lnf_b, h);

    // logits = h @ wte^T
    gemm_tc<128,128,32,64,0,true,false><<<dim3((VV + 127) / 128, BT / 128), 256>>>(
        h, wte, nullptr, nullptr, out, BT, VV, CC, CC, CC, VV, 1.f,
        0,0,0,0,0,0, 0);

    nll_k<<<BT, 256>>>(out, target, nll);
    mean_k<<<1, 256>>>(nll, out + (out_size - 1));
}